// round 15
// baseline (speedup 1.0000x reference)
#include <cuda_runtime.h>

#define NN      20000
#define IN_DIM  64
#define H       32
#define E_EDGES 200000
#define ED      8
#define EH      32
#define H2      1024   // H*H
#define CAP     64     // per-node bucket capacity (Poisson(10): P(deg>64) ~ 0)

typedef unsigned long long u64;

// ---------------- device scratch ----------------
__device__ float g_xemb[NN * H];
__device__ float g_nb[NN * H];
__device__ float g_Wp[H * H2];                    // k-group-major: [h][k/4][o][k%4]
__device__ float g_h1[(size_t)E_EDGES * EH];      // 25.6 MB per-edge hidden
__device__ int   g_cnt[NN];                       // src degree
__device__ int   g_cnt_dst[NN];                   // dst degree
__device__ int2  g_pair[NN * CAP];                // per-src: (edge id, dst slot)
__device__ float g_msg[((size_t)NN * CAP + 1) * H];  // dst-slotted messages (+dump row)

// ---------------- K1: embed + nb + Wp permute + zero counters (R9-exact) ----------------
__global__ __launch_bounds__(256) void k_embed(const float* __restrict__ x,
                                               const float* __restrict__ W0,
                                               const float* __restrict__ b0,
                                               const float* __restrict__ be2,
                                               const float* __restrict__ We2) {
    __shared__ float W0s[IN_DIM * H];
    __shared__ float be2s[H2];
    __shared__ float xrow[8][IN_DIM];
    int tid = threadIdx.x;
    for (int i = tid; i < IN_DIM * H; i += 256) W0s[i] = W0[i];
    for (int i = tid; i < H2; i += 256)         be2s[i] = be2[i];

    int g = blockIdx.x * 256 + tid;               // 0..639999
    if (g < NN)          g_cnt[g] = 0;
    else if (g < 2 * NN) g_cnt_dst[g - NN] = 0;
    if (g < H * H2) {                             // permute We2 -> Wp (k-group-major)
        float v = We2[g];                         // g = k*1024 + h*32 + o
        int k = g >> 10, h = (g >> 5) & 31, o = g & 31;
        g_Wp[h * H2 + (k >> 2) * 128 + o * 4 + (k & 3)] = v;
    }

    int w = tid >> 5, lane = tid & 31;
    int n = blockIdx.x * 8 + w;
    xrow[w][lane]      = x[n * IN_DIM + lane];
    xrow[w][lane + 32] = x[n * IN_DIM + 32 + lane];
    __syncthreads();

    float acc = b0[lane];
#pragma unroll
    for (int i = 0; i < IN_DIM; i++) acc += xrow[w][i] * W0s[i * H + lane];
    float xe = fmaxf(acc, 0.0f);
    g_xemb[n * H + lane] = xe;

    float nb = 0.0f;
#pragma unroll
    for (int h = 0; h < H; h++) {
        float xh = __shfl_sync(0xffffffffu, xe, h);
        nb += xh * be2s[h * H + lane];
    }
    g_nb[n * H + lane] = nb;
}

// ---------------- K2: build — warp per 8 edges; src + dst slot assignment ----------------
__global__ __launch_bounds__(256) void k_build(const float* __restrict__ edge_attr,
                                               const float* __restrict__ We1,
                                               const float* __restrict__ be1,
                                               const int* __restrict__ ei) {
    __shared__ float W1s[ED * EH];
    __shared__ float b1s[EH];
    __shared__ float eas[8][64];
    int tid = threadIdx.x;
    if (tid < ED * EH) W1s[tid] = We1[tid];
    if (tid < EH)      b1s[tid] = be1[tid];
    __syncthreads();

    int w = tid >> 5, lane = tid & 31;
    int we = blockIdx.x * 8 + w;                  // 25000 warp-edge-groups
    int e0 = we * 8;

    float2 ea2 = ((const float2*)edge_attr)[we * 32 + lane];
    eas[w][lane * 2]     = ea2.x;
    eas[w][lane * 2 + 1] = ea2.y;
    __syncwarp();

    float acc[8];
#pragma unroll
    for (int e = 0; e < 8; e++) acc[e] = b1s[lane];
#pragma unroll
    for (int d = 0; d < ED; d++) {
        float wv = W1s[d * EH + lane];
#pragma unroll
        for (int e = 0; e < 8; e++) acc[e] += eas[w][e * 8 + d] * wv;
    }
#pragma unroll
    for (int e = 0; e < 8; e++)
        g_h1[(size_t)(e0 + e) * EH + lane] = fmaxf(acc[e], 0.0f);

    if (lane < 8) {
        int e = e0 + lane;
        int s = ei[e];
        int d = ei[E_EDGES + e];
        if ((unsigned)s < NN && (unsigned)d < NN) {
            int p = atomicAdd(&g_cnt[s], 1);
            int q = atomicAdd(&g_cnt_dst[d], 1);
            if (p < CAP) {
                int slot = (q < CAP) ? d * CAP + q : NN * CAP;   // dump row if overflow
                g_pair[s * CAP + p] = make_int2(e, slot);
            }
        }
    }
}

// ---------------- K3: FUSED messages — ballot h-loop + pair prefetch ----------------
#define MSG_T 768
#define NWARPS (MSG_T / 32)                       // 24 warps/block
__global__ __launch_bounds__(MSG_T, 1) void k_msg() {
    extern __shared__ float Wps[];                // 32768 floats, k-group-major
    int tid = threadIdx.x;
    for (int i = tid; i < (H * H2) / 4; i += MSG_T)
        ((float4*)Wps)[i] = ((const float4*)g_Wp)[i];
    __syncthreads();

    int w = tid >> 5, lane = tid & 31;
    const int ngrp = (NN + NWARPS - 1) / NWARPS;  // 834

    for (int grp = blockIdx.x; grp < ngrp; grp += gridDim.x) {
        int n = grp * NWARPS + w;
        if (n >= NN) continue;
        int deg = g_cnt[n];
        if (deg > CAP) deg = CAP;
        if (deg == 0) continue;

        float xe  = g_xemb[n * H + lane];
        float nbv = g_nb[n * H + lane];
        const int2* pb = &g_pair[n * CAP];
        int2 pnext = pb[0];                       // prefetch: latency hides under Tf build

        // Tf build: iterate ONLY active h (ballot), conflict-free LDS.128
        unsigned am = __ballot_sync(0xffffffffu, xe != 0.0f);   // bit h = activity
        u64 Tp[16];
#pragma unroll
        for (int i = 0; i < 16; i++) Tp[i] = 0ull;

        while (am) {
            int h = __ffs(am) - 1;
            am &= am - 1;
            float xh = __shfl_sync(0xffffffffu, xe, h);
            u64 xd;
            asm("mov.b64 %0, {%1, %1};" : "=l"(xd) : "r"(__float_as_uint(xh)));
            const ulonglong2* p = (const ulonglong2*)(Wps + h * H2) + lane;
#pragma unroll
            for (int i = 0; i < 8; i++) {
                ulonglong2 v = p[i * 32];         // compile-time offsets, conflict-free
                asm("fma.rn.f32x2 %0, %1, %2, %0;" : "+l"(Tp[2*i])   : "l"(xd), "l"(v.x));
                asm("fma.rn.f32x2 %0, %1, %2, %0;" : "+l"(Tp[2*i+1]) : "l"(xd), "l"(v.y));
            }
        }

        // Edge loop: slot stores, pair prefetch, 4 independent FMA chains
#pragma unroll 1
        for (int j = 0; j < deg; j++) {
            int2 pc = pnext;
            if (j + 1 < deg) pnext = pb[j + 1];   // prefetch next pair during compute
            const ulonglong2* hp = (const ulonglong2*)(g_h1 + (size_t)pc.x * EH);
            ulonglong2 hv[8];
#pragma unroll
            for (int i = 0; i < 8; i++) hv[i] = hp[i];   // batched broadcast LDG.128
            u64 a0 = 0ull, a1 = 0ull, a2 = 0ull, a3 = 0ull;
#pragma unroll
            for (int i = 0; i < 4; i++) {         // 4 chains, depth 4
                asm("fma.rn.f32x2 %0, %1, %2, %0;" : "+l"(a0) : "l"(hv[2*i].x),   "l"(Tp[4*i]));
                asm("fma.rn.f32x2 %0, %1, %2, %0;" : "+l"(a1) : "l"(hv[2*i].y),   "l"(Tp[4*i+1]));
                asm("fma.rn.f32x2 %0, %1, %2, %0;" : "+l"(a2) : "l"(hv[2*i+1].x), "l"(Tp[4*i+2]));
                asm("fma.rn.f32x2 %0, %1, %2, %0;" : "+l"(a3) : "l"(hv[2*i+1].y), "l"(Tp[4*i+3]));
            }
            asm("add.rn.f32x2 %0, %0, %1;" : "+l"(a0) : "l"(a1));
            asm("add.rn.f32x2 %0, %0, %1;" : "+l"(a2) : "l"(a3));
            asm("add.rn.f32x2 %0, %0, %1;" : "+l"(a0) : "l"(a2));
            unsigned lo, hi;
            asm("mov.b64 {%0, %1}, %2;" : "=r"(lo), "=r"(hi) : "l"(a0));
            g_msg[(size_t)pc.y * H + lane] = nbv + __uint_as_float(lo) + __uint_as_float(hi);
        }
    }
}

// ---------------- K4: slot gather + root + GRU (R9-exact fat version) ----------------
__global__ __launch_bounds__(256) void k_final(const float* __restrict__ root,
                                               const float* __restrict__ bconv,
                                               const float* __restrict__ w_ih,
                                               const float* __restrict__ w_hh,
                                               const float* __restrict__ b_ih,
                                               const float* __restrict__ b_hh,
                                               float* __restrict__ out) {
    __shared__ float roots[H * H];
    __shared__ float wihT[H * 96];
    __shared__ float whhT[H * 96];
    __shared__ float bihs[96], bhhs[96], bconvs[H];
    int tid = threadIdx.x;
    for (int i = tid; i < H * H; i += 256) roots[i] = root[i];
    for (int i = tid; i < H * 96; i += 256) {
        int h = i / 96, j = i - h * 96;
        wihT[i] = w_ih[j * H + h];
        whhT[i] = w_hh[j * H + h];
    }
    if (tid < 96) { bihs[tid] = b_ih[tid]; bhhs[tid] = b_hh[tid]; }
    if (tid < H)  bconvs[tid] = bconv[tid];
    __syncthreads();

    int lane = tid & 31, w = tid >> 5;
    int n = (blockIdx.x * 256 + tid) >> 5;        // 2500 blocks x 8 warps

    int deg = g_cnt_dst[n];
    if (deg > CAP) deg = CAP;
    float s = 0.0f;
    const float* mp = g_msg + (size_t)n * CAP * H + lane;
    for (int j = 0; j < deg; j++) s += mp[j * H];

    float xe = g_xemb[n * H + lane];
    float conv = s + bconvs[lane];
#pragma unroll
    for (int h = 0; h < H; h++) {
        float xh = __shfl_sync(0xffffffffu, xe, h);
        conv += xh * roots[h * H + lane];
    }

    float ar = bihs[lane], az = bihs[32 + lane], an = bihs[64 + lane];
    float hr = bhhs[lane], hz = bhhs[32 + lane], hn = bhhs[64 + lane];
#pragma unroll
    for (int h = 0; h < H; h++) {
        float ch = __shfl_sync(0xffffffffu, conv, h);
        float xh = __shfl_sync(0xffffffffu, xe, h);
        const float* wi = &wihT[h * 96];
        const float* wh = &whhT[h * 96];
        ar += ch * wi[lane];      az += ch * wi[32 + lane];  an += ch * wi[64 + lane];
        hr += xh * wh[lane];      hz += xh * wh[32 + lane];  hn += xh * wh[64 + lane];
    }

    float r  = 1.0f / (1.0f + expf(-(ar + hr)));
    float z  = 1.0f / (1.0f + expf(-(az + hz)));
    float nn = tanhf(an + r * hn);
    out[n * H + lane] = (1.0f - z) * nn + z * xe;
}

// ---------------- launcher ----------------
extern "C" void kernel_launch(void* const* d_in, const int* in_sizes, int n_in,
                              void* d_out, int out_size) {
    const float* x         = (const float*)d_in[0];
    const float* edge_attr = (const float*)d_in[1];
    const float* W0        = (const float*)d_in[2];
    const float* b0        = (const float*)d_in[3];
    const float* We1       = (const float*)d_in[4];
    const float* be1       = (const float*)d_in[5];
    const float* We2       = (const float*)d_in[6];
    const float* be2       = (const float*)d_in[7];
    const float* root      = (const float*)d_in[8];
    const float* bconv     = (const float*)d_in[9];
    const float* w_ih      = (const float*)d_in[10];
    const float* w_hh      = (const float*)d_in[11];
    const float* b_ih      = (const float*)d_in[12];
    const float* b_hh      = (const float*)d_in[13];
    const int*   ei        = (const int*)d_in[14];
    float* out = (float*)d_out;

    size_t smem_msg = (size_t)(H * H2) * sizeof(float);   // 131072 B
    cudaFuncSetAttribute(k_msg, cudaFuncAttributeMaxDynamicSharedMemorySize, (int)smem_msg);

    k_embed<<<NN * H / 256, 256>>>(x, W0, b0, be2, We2);       // 1
    k_build<<<E_EDGES / 64, 256>>>(edge_attr, We1, be1, ei);   // 2
    k_msg  <<<148, MSG_T, smem_msg>>>();                       // 3
    k_final<<<NN / 8, 256>>>(root, bconv, w_ih, w_hh, b_ih, b_hh, out);  // 4  <- profiled slot
}

// round 16
// speedup vs baseline: 1.2240x; 1.2240x over previous
#include <cuda_runtime.h>

#define NN      20000
#define IN_DIM  64
#define H       32
#define E_EDGES 200000
#define ED      8
#define EH      32
#define H2      1024   // H*H
#define CAP     64     // per-node bucket capacity (Poisson(10): P(deg>64) ~ 0)

typedef unsigned long long u64;

// ---------------- device scratch ----------------
__device__ float g_xemb[NN * H];
__device__ float g_nb[NN * H];
__device__ float g_convX[NN * H];                 // xe@root + bconv
__device__ float g_gh[NN * 96];                   // xe@w_hh^T + b_hh
__device__ float g_Wp[H * H2];                    // k-group-major: [h][k/4][o][k%4]
__device__ float g_wihT[H * 96];                  // pre-transposed GRU weights
__device__ float g_whhT[H * 96];
__device__ float g_h1[(size_t)E_EDGES * EH];      // 25.6 MB per-edge hidden
__device__ int   g_cnt[NN];                       // src degree
__device__ int   g_cnt_dst[NN];                   // dst degree
__device__ int2  g_pair[NN * CAP];                // per-src: (edge id, dst slot)
__device__ float g_msg[((size_t)NN * CAP + 1) * H];  // dst-slotted messages (+dump row)

// ---------------- K1: embed + nb + permutes + zero counters ----------------
__global__ __launch_bounds__(256) void k_embed(const float* __restrict__ x,
                                               const float* __restrict__ W0,
                                               const float* __restrict__ b0,
                                               const float* __restrict__ be2,
                                               const float* __restrict__ We2,
                                               const float* __restrict__ w_ih,
                                               const float* __restrict__ w_hh) {
    __shared__ float W0s[IN_DIM * H];
    __shared__ float be2s[H2];
    __shared__ float xrow[8][IN_DIM];
    int tid = threadIdx.x;
    for (int i = tid; i < IN_DIM * H; i += 256) W0s[i] = W0[i];
    for (int i = tid; i < H2; i += 256)         be2s[i] = be2[i];

    int g = blockIdx.x * 256 + tid;               // 0..639999
    if (g < NN)          g_cnt[g] = 0;
    else if (g < 2 * NN) g_cnt_dst[g - NN] = 0;
    if (g < H * H2) {                             // permute We2 -> Wp (k-group-major)
        float v = We2[g];                         // g = k*1024 + h*32 + o
        int k = g >> 10, h = (g >> 5) & 31, o = g & 31;
        g_Wp[h * H2 + (k >> 2) * 128 + o * 4 + (k & 3)] = v;
    }
    if (g >= H * H2 && g < H * H2 + H * 96) {     // one-time GRU weight transpose
        int i = g - H * H2;                       // i = h*96 + j
        int h = i / 96, j = i - h * 96;
        g_wihT[i] = w_ih[j * H + h];
        g_whhT[i] = w_hh[j * H + h];
    }

    int w = tid >> 5, lane = tid & 31;
    int n = blockIdx.x * 8 + w;
    xrow[w][lane]      = x[n * IN_DIM + lane];
    xrow[w][lane + 32] = x[n * IN_DIM + 32 + lane];
    __syncthreads();

    float acc = b0[lane];
#pragma unroll
    for (int i = 0; i < IN_DIM; i++) acc += xrow[w][i] * W0s[i * H + lane];
    float xe = fmaxf(acc, 0.0f);
    g_xemb[n * H + lane] = xe;

    float nb = 0.0f;
#pragma unroll
    for (int h = 0; h < H; h++) {
        float xh = __shfl_sync(0xffffffffu, xe, h);
        nb += xh * be2s[h * H + lane];
    }
    g_nb[n * H + lane] = nb;
}

// ---------------- K2: build — warp per 8 edges; src + dst slot assignment ----------------
__global__ __launch_bounds__(256) void k_build(const float* __restrict__ edge_attr,
                                               const float* __restrict__ We1,
                                               const float* __restrict__ be1,
                                               const int* __restrict__ ei) {
    __shared__ float W1s[ED * EH];
    __shared__ float b1s[EH];
    __shared__ float eas[8][64];
    int tid = threadIdx.x;
    if (tid < ED * EH) W1s[tid] = We1[tid];
    if (tid < EH)      b1s[tid] = be1[tid];
    __syncthreads();

    int w = tid >> 5, lane = tid & 31;
    int we = blockIdx.x * 8 + w;                  // 25000 warp-edge-groups
    int e0 = we * 8;

    float2 ea2 = ((const float2*)edge_attr)[we * 32 + lane];
    eas[w][lane * 2]     = ea2.x;
    eas[w][lane * 2 + 1] = ea2.y;
    __syncwarp();

    float acc[8];
#pragma unroll
    for (int e = 0; e < 8; e++) acc[e] = b1s[lane];
#pragma unroll
    for (int d = 0; d < ED; d++) {
        float wv = W1s[d * EH + lane];
#pragma unroll
        for (int e = 0; e < 8; e++) acc[e] += eas[w][e * 8 + d] * wv;
    }
#pragma unroll
    for (int e = 0; e < 8; e++)
        g_h1[(size_t)(e0 + e) * EH + lane] = fmaxf(acc[e], 0.0f);

    if (lane < 8) {
        int e = e0 + lane;
        int s = ei[e];
        int d = ei[E_EDGES + e];
        if ((unsigned)s < NN && (unsigned)d < NN) {
            int p = atomicAdd(&g_cnt[s], 1);
            int q = atomicAdd(&g_cnt_dst[d], 1);
            if (p < CAP) {
                int slot = (q < CAP) ? d * CAP + q : NN * CAP;   // dump row if overflow
                g_pair[s * CAP + p] = make_int2(e, slot);
            }
        }
    }
}

// ---------------- K3: precompute convX + gh (coalesced weight preamble) ----------------
__global__ __launch_bounds__(256) void k_pre(const float* __restrict__ root,
                                             const float* __restrict__ bconv,
                                             const float* __restrict__ b_hh) {
    __shared__ float roots[H * H];
    __shared__ float whhT[H * 96];
    __shared__ float bconvs[H], bhhs[96];
    int tid = threadIdx.x;
    for (int i = tid; i < H * H; i += 256)  roots[i] = root[i];
    for (int i = tid; i < H * 96; i += 256) whhT[i] = g_whhT[i];   // linear, coalesced
    if (tid < H)  bconvs[tid] = bconv[tid];
    if (tid < 96) bhhs[tid] = b_hh[tid];
    __syncthreads();

    int lane = tid & 31, w = tid >> 5;

#pragma unroll 1
    for (int it = 0; it < 4; it++) {              // 625 blocks x 4 x 8 nodes = 20000
        int n = blockIdx.x * 32 + it * 8 + w;
        float xe = g_xemb[n * H + lane];

        float cvx = bconvs[lane];
        float g0 = bhhs[lane], g1 = bhhs[32 + lane], g2 = bhhs[64 + lane];
#pragma unroll
        for (int h = 0; h < H; h++) {
            float xh = __shfl_sync(0xffffffffu, xe, h);
            cvx += xh * roots[h * H + lane];
            const float* wh = &whhT[h * 96];
            g0 += xh * wh[lane];
            g1 += xh * wh[32 + lane];
            g2 += xh * wh[64 + lane];
        }
        g_convX[n * H + lane]    = cvx;
        g_gh[n * 96 + lane]      = g0;
        g_gh[n * 96 + 32 + lane] = g1;
        g_gh[n * 96 + 64 + lane] = g2;
    }
}

// ---------------- K4: FUSED messages — ballot h-loop + pair prefetch ----------------
#define MSG_T 768
#define NWARPS (MSG_T / 32)                       // 24 warps/block
__global__ __launch_bounds__(MSG_T, 1) void k_msg() {
    extern __shared__ float Wps[];                // 32768 floats, k-group-major
    int tid = threadIdx.x;
    for (int i = tid; i < (H * H2) / 4; i += MSG_T)
        ((float4*)Wps)[i] = ((const float4*)g_Wp)[i];
    __syncthreads();

    int w = tid >> 5, lane = tid & 31;
    const int ngrp = (NN + NWARPS - 1) / NWARPS;  // 834

    for (int grp = blockIdx.x; grp < ngrp; grp += gridDim.x) {
        int n = grp * NWARPS + w;
        if (n >= NN) continue;
        int deg = g_cnt[n];
        if (deg > CAP) deg = CAP;
        if (deg == 0) continue;

        float xe  = g_xemb[n * H + lane];
        float nbv = g_nb[n * H + lane];
        const int2* pb = &g_pair[n * CAP];
        int2 pnext = pb[0];                       // prefetch: hides under Tf build

        // Tf build: iterate ONLY active h (ballot), conflict-free LDS.128
        unsigned am = __ballot_sync(0xffffffffu, xe != 0.0f);
        u64 Tp[16];
#pragma unroll
        for (int i = 0; i < 16; i++) Tp[i] = 0ull;

        while (am) {
            int h = __ffs(am) - 1;
            am &= am - 1;
            float xh = __shfl_sync(0xffffffffu, xe, h);
            u64 xd;
            asm("mov.b64 %0, {%1, %1};" : "=l"(xd) : "r"(__float_as_uint(xh)));
            const ulonglong2* p = (const ulonglong2*)(Wps + h * H2) + lane;
#pragma unroll
            for (int i = 0; i < 8; i++) {
                ulonglong2 v = p[i * 32];
                asm("fma.rn.f32x2 %0, %1, %2, %0;" : "+l"(Tp[2*i])   : "l"(xd), "l"(v.x));
                asm("fma.rn.f32x2 %0, %1, %2, %0;" : "+l"(Tp[2*i+1]) : "l"(xd), "l"(v.y));
            }
        }

        // Edge loop: slot stores, pair prefetch, 4 independent FMA chains
#pragma unroll 1
        for (int j = 0; j < deg; j++) {
            int2 pc = pnext;
            if (j + 1 < deg) pnext = pb[j + 1];
            const ulonglong2* hp = (const ulonglong2*)(g_h1 + (size_t)pc.x * EH);
            ulonglong2 hv[8];
#pragma unroll
            for (int i = 0; i < 8; i++) hv[i] = hp[i];
            u64 a0 = 0ull, a1 = 0ull, a2 = 0ull, a3 = 0ull;
#pragma unroll
            for (int i = 0; i < 4; i++) {
                asm("fma.rn.f32x2 %0, %1, %2, %0;" : "+l"(a0) : "l"(hv[2*i].x),   "l"(Tp[4*i]));
                asm("fma.rn.f32x2 %0, %1, %2, %0;" : "+l"(a1) : "l"(hv[2*i].y),   "l"(Tp[4*i+1]));
                asm("fma.rn.f32x2 %0, %1, %2, %0;" : "+l"(a2) : "l"(hv[2*i+1].x), "l"(Tp[4*i+2]));
                asm("fma.rn.f32x2 %0, %1, %2, %0;" : "+l"(a3) : "l"(hv[2*i+1].y), "l"(Tp[4*i+3]));
            }
            asm("add.rn.f32x2 %0, %0, %1;" : "+l"(a0) : "l"(a1));
            asm("add.rn.f32x2 %0, %0, %1;" : "+l"(a2) : "l"(a3));
            asm("add.rn.f32x2 %0, %0, %1;" : "+l"(a0) : "l"(a2));
            unsigned lo, hi;
            asm("mov.b64 {%0, %1}, %2;" : "=r"(lo), "=r"(hi) : "l"(a0));
            g_msg[(size_t)pc.y * H + lane] = nbv + __uint_as_float(lo) + __uint_as_float(hi);
        }
    }
}

// ---------------- K5: slot gather + single matmul + GRU (coalesced preamble) ----------------
__global__ __launch_bounds__(256) void k_final(const float* __restrict__ b_ih,
                                               float* __restrict__ out) {
    __shared__ float wihT[H * 96];
    __shared__ float bihs[96];
    int tid = threadIdx.x;
    for (int i = tid; i < H * 96; i += 256) wihT[i] = g_wihT[i];   // linear, coalesced
    if (tid < 96) bihs[tid] = b_ih[tid];
    __syncthreads();

    int lane = tid & 31, w = tid >> 5;

#pragma unroll 1
    for (int it = 0; it < 4; it++) {              // 625 blocks x 4 x 8 nodes = 20000
        int n = blockIdx.x * 32 + it * 8 + w;

        float xe  = g_xemb[n * H + lane];
        float hr  = g_gh[n * 96 + lane];
        float hz  = g_gh[n * 96 + 32 + lane];
        float hn  = g_gh[n * 96 + 64 + lane];
        float cvx = g_convX[n * H + lane];

        int deg = g_cnt_dst[n];
        if (deg > CAP) deg = CAP;
        float s = 0.0f;
        const float* mp = g_msg + (size_t)n * CAP * H + lane;
        for (int j = 0; j < deg; j++) s += mp[j * H];

        float conv = s + cvx;

        float ar = bihs[lane], az = bihs[32 + lane], an = bihs[64 + lane];
#pragma unroll
        for (int h = 0; h < H; h++) {
            float ch = __shfl_sync(0xffffffffu, conv, h);
            const float* wi = &wihT[h * 96];
            ar += ch * wi[lane];
            az += ch * wi[32 + lane];
            an += ch * wi[64 + lane];
        }

        float r  = 1.0f / (1.0f + expf(-(ar + hr)));
        float z  = 1.0f / (1.0f + expf(-(az + hz)));
        float nn = tanhf(an + r * hn);
        out[n * H + lane] = (1.0f - z) * nn + z * xe;
    }
}

// ---------------- launcher ----------------
extern "C" void kernel_launch(void* const* d_in, const int* in_sizes, int n_in,
                              void* d_out, int out_size) {
    const float* x         = (const float*)d_in[0];
    const float* edge_attr = (const float*)d_in[1];
    const float* W0        = (const float*)d_in[2];
    const float* b0        = (const float*)d_in[3];
    const float* We1       = (const float*)d_in[4];
    const float* be1       = (const float*)d_in[5];
    const float* We2       = (const float*)d_in[6];
    const float* be2       = (const float*)d_in[7];
    const float* root      = (const float*)d_in[8];
    const float* bconv     = (const float*)d_in[9];
    const float* w_ih      = (const float*)d_in[10];
    const float* w_hh      = (const float*)d_in[11];
    const float* b_ih      = (const float*)d_in[12];
    const float* b_hh      = (const float*)d_in[13];
    const int*   ei        = (const int*)d_in[14];
    float* out = (float*)d_out;

    size_t smem_msg = (size_t)(H * H2) * sizeof(float);   // 131072 B
    cudaFuncSetAttribute(k_msg, cudaFuncAttributeMaxDynamicSharedMemorySize, (int)smem_msg);

    k_embed<<<NN * H / 256, 256>>>(x, W0, b0, be2, We2, w_ih, w_hh);  // 1
    k_build<<<E_EDGES / 64, 256>>>(edge_attr, We1, be1, ei);          // 2
    k_pre  <<<625, 256>>>(root, bconv, b_hh);                         // 3
    k_msg  <<<148, MSG_T, smem_msg>>>();                              // 4  <- profiled slot
    k_final<<<625, 256>>>(b_ih, out);                                 // 5
}